// round 1
// baseline (speedup 1.0000x reference)
#include <cuda_runtime.h>

#define BB 16
#define CC 3
#define HH 256
#define WW 256
#define MM 100
#define HW (HH * WW)
#define OUT_PIX (BB * MM * MM)

// Channel-interleaved input: [B, H, W] of float4 (c0,c1,c2,0). 16.8 MB static.
__device__ float4 g_packed[BB * HW];

__global__ void pack_kernel(const float* __restrict__ x) {
    int idx = blockIdx.x * blockDim.x + threadIdx.x;
    if (idx >= BB * HW) return;
    int b = idx >> 16;           // HW = 65536
    int p = idx & (HW - 1);
    const float* xb = x + (size_t)b * CC * HW + p;
    float4 v;
    v.x = xb[0];
    v.y = xb[HW];
    v.z = xb[2 * HW];
    v.w = 0.0f;
    g_packed[idx] = v;
}

__global__ void __launch_bounds__(128) stn_kernel(const float* __restrict__ theta,
                                                  float* __restrict__ out) {
    int idx = blockIdx.x * blockDim.x + threadIdx.x;
    if (idx >= OUT_PIX) return;
    int b = idx / (MM * MM);
    int r = idx - b * (MM * MM);
    int i = r / MM;
    int j = r - i * MM;

    const float* t = theta + b * 6;
    float t00 = __ldg(t + 0), t01 = __ldg(t + 1), t02 = __ldg(t + 2);
    float t10 = __ldg(t + 3), t11 = __ldg(t + 4), t12 = __ldg(t + 5);

    // affine_grid base coords (align_corners=False pixel centers)
    float lx = (j + 0.5f) * (2.0f / MM) - 1.0f;
    float ly = (i + 0.5f) * (2.0f / MM) - 1.0f;
    float gx = fmaf(t00, lx, fmaf(t01, ly, t02));
    float gy = fmaf(t10, lx, fmaf(t11, ly, t12));

    // unnormalize: ix = ((gx+1)*W - 1)/2 = gx*128 + 127.5
    float ixb = fmaf(gx, 0.5f * WW, 0.5f * WW - 0.5f);
    float iyb = fmaf(gy, 0.5f * HH, 0.5f * HH - 0.5f);

    // per-tap pixel-space step: dx = (kx-5)/6, scale = 1/99, times W/2
    const float cstep = (0.5f * WW) / (6.0f * 99.0f);
    float ux = t00 * cstep;  // d(ix)/d(kx)
    float uy = t10 * cstep;  // d(iy)/d(kx)
    float vx = t01 * cstep;  // d(ix)/d(ky)
    float vy = t11 * cstep;  // d(iy)/d(ky)

    // separable 1D weights (registers; init loop fully unrolled)
    float wk[11];
    float wsum = 0.0f;
#pragma unroll
    for (int k = 0; k < 11; k++) {
        float d = (float)(k - 5) * (1.0f / 6.0f);
        wk[k] = expf(-8.0f * d * d);
        wsum += wk[k];
    }
    float inv = 1.0f / (wsum * wsum);

    const float4* __restrict__ base = g_packed + b * HW;

    float acc0 = 0.0f, acc1 = 0.0f, acc2 = 0.0f;

#pragma unroll 1
    for (int ky = 0; ky < 11; ky++) {
        float dky = (float)(ky - 5);
        // recompute wyk to avoid dynamic register-array indexing (no spills)
        float dd = dky * (1.0f / 6.0f);
        float wyk = expf(-8.0f * dd * dd);
        float ixr = fmaf(dky, vx, ixb);
        float iyr = fmaf(dky, vy, iyb);
#pragma unroll
        for (int kx = 0; kx < 11; kx++) {
            float dkx = (float)(kx - 5);
            float ix = fmaf(dkx, ux, ixr);
            float iy = fmaf(dkx, uy, iyr);

            float x0f = floorf(ix);
            float y0f = floorf(iy);
            float fx = ix - x0f;
            float fy = iy - y0f;
            int x0 = (int)x0f;
            int y0 = (int)y0f;
            int x1 = x0 + 1;
            int y1 = y0 + 1;

            // zeros padding: per-edge validity folded into the 1D weights
            float wx0 = ((unsigned)x0 < (unsigned)WW) ? (1.0f - fx) : 0.0f;
            float wx1 = ((unsigned)x1 < (unsigned)WW) ? fx : 0.0f;
            float wy0 = ((unsigned)y0 < (unsigned)HH) ? (1.0f - fy) : 0.0f;
            float wy1 = ((unsigned)y1 < (unsigned)HH) ? fy : 0.0f;

            int xc0 = min(max(x0, 0), WW - 1);
            int xc1 = min(max(x1, 0), WW - 1);
            int yc0 = min(max(y0, 0), HH - 1);
            int yc1 = min(max(y1, 0), HH - 1);

            int r0 = yc0 * WW;
            int r1 = yc1 * WW;
            float4 v00 = base[r0 + xc0];
            float4 v01 = base[r0 + xc1];
            float4 v10 = base[r1 + xc0];
            float4 v11 = base[r1 + xc1];

            float wgt = wyk * wk[kx];
            float w00 = wy0 * wx0 * wgt;
            float w01 = wy0 * wx1 * wgt;
            float w10 = wy1 * wx0 * wgt;
            float w11 = wy1 * wx1 * wgt;

            acc0 = fmaf(w00, v00.x, acc0);
            acc0 = fmaf(w01, v01.x, acc0);
            acc0 = fmaf(w10, v10.x, acc0);
            acc0 = fmaf(w11, v11.x, acc0);
            acc1 = fmaf(w00, v00.y, acc1);
            acc1 = fmaf(w01, v01.y, acc1);
            acc1 = fmaf(w10, v10.y, acc1);
            acc1 = fmaf(w11, v11.y, acc1);
            acc2 = fmaf(w00, v00.z, acc2);
            acc2 = fmaf(w01, v01.z, acc2);
            acc2 = fmaf(w10, v10.z, acc2);
            acc2 = fmaf(w11, v11.z, acc2);
        }
    }

    // fold the global (sum of weights)^2 normalization once at the end
    float* ob = out + b * (CC * MM * MM) + r;
    ob[0]            = acc0 * inv;
    ob[MM * MM]      = acc1 * inv;
    ob[2 * MM * MM]  = acc2 * inv;
}

extern "C" void kernel_launch(void* const* d_in, const int* in_sizes, int n_in,
                              void* d_out, int out_size) {
    // robust input ordering: theta has 96 elements, x has 3,145,728
    const float* x = (const float*)d_in[0];
    const float* th = (const float*)d_in[1];
    if (n_in >= 2 && in_sizes[0] == 96) {
        x = (const float*)d_in[1];
        th = (const float*)d_in[0];
    }
    float* out = (float*)d_out;

    {
        int n = BB * HW;
        int tpb = 256;
        pack_kernel<<<(n + tpb - 1) / tpb, tpb>>>(x);
    }
    {
        int n = OUT_PIX;
        int tpb = 128;
        stn_kernel<<<(n + tpb - 1) / tpb, tpb>>>(th, out);
    }
    (void)out_size;
}

// round 2
// speedup vs baseline: 2.4340x; 2.4340x over previous
#include <cuda_runtime.h>
#include <cuda_fp16.h>

#define BB 16
#define CC 3
#define HH 256
#define WW 256
#define MM 100
#define HW (HH * WW)
#define OUT_PIX (BB * MM * MM)

// Packed fp16 input, pair-duplicated by parity.
// Per row (b,y): 256 uint4 entries.
//   entries [0,128):   pair k = pixels (2k, 2k+1)      (even-start pairs)
//   entries [128,256): pair k = pixels (2k+1, 2k+2)    (odd-start pairs)
// Each pixel = 8B: (half2 c0c1, half2 c2,0). Pair = 16B = uint4.
// Total: 16 * 256 * 256 * 16B = 16.8 MB (L2-resident).
__device__ uint4 g_packed[BB * HH * 256];

__global__ void pack_kernel(const float* __restrict__ x) {
    int idx = blockIdx.x * blockDim.x + threadIdx.x;
    if (idx >= BB * HW) return;
    int b = idx >> 16;                 // HW = 65536
    int p = idx & (HW - 1);
    int xx = p & 255;
    const float* xb = x + (size_t)b * CC * HW + p;
    __half2 c01 = __halves2half2(__float2half(xb[0]), __float2half(xb[HW]));
    __half2 c2p = __halves2half2(__float2half(xb[2 * HW]), __float2half(0.0f));
    uint2 v;
    v.x = *reinterpret_cast<unsigned int*>(&c01);
    v.y = *reinterpret_cast<unsigned int*>(&c2p);
    uint2* buf2 = reinterpret_cast<uint2*>(g_packed);
    int rowu = (idx >> 8) << 9;        // (b*256+y) * 512 uint2 units per row
    buf2[rowu + xx] = v;               // even-parity region: pixel x at unit x
    if (xx >= 1) buf2[rowu + 256 + xx - 1] = v;  // odd-parity region shifted by 1
}

__device__ __forceinline__ void accum(unsigned c01, unsigned c2w, float w,
                                      float& a0, float& a1, float& a2) {
    __half2 h01 = *reinterpret_cast<const __half2*>(&c01);
    float2 f01 = __half22float2(h01);
    float f2 = __half2float(reinterpret_cast<const __half*>(&c2w)[0]);
    a0 = fmaf(w, f01.x, a0);
    a1 = fmaf(w, f01.y, a1);
    a2 = fmaf(w, f2, a2);
}

// 2 threads per output pixel: thread half h handles ky = h, h+2, ...
__global__ void __launch_bounds__(128) stn_kernel(const float* __restrict__ theta,
                                                  float* __restrict__ out) {
    int t = blockIdx.x * blockDim.x + threadIdx.x;
    if (t >= OUT_PIX * 2) return;
    int half = t & 1;
    int idx = t >> 1;
    int b = idx / (MM * MM);
    int r = idx - b * (MM * MM);
    int i = r / MM;
    int j = r - i * MM;

    const float* th = theta + b * 6;
    float t00 = __ldg(th + 0), t01 = __ldg(th + 1), t02 = __ldg(th + 2);
    float t10 = __ldg(th + 3), t11 = __ldg(th + 4), t12 = __ldg(th + 5);

    // affine_grid base coords (align_corners=False pixel centers)
    float lx = (j + 0.5f) * (2.0f / MM) - 1.0f;
    float ly = (i + 0.5f) * (2.0f / MM) - 1.0f;
    float gx = fmaf(t00, lx, fmaf(t01, ly, t02));
    float gy = fmaf(t10, lx, fmaf(t11, ly, t12));

    // unnormalize to pixel space
    float ixb = fmaf(gx, 0.5f * WW, 0.5f * WW - 0.5f);
    float iyb = fmaf(gy, 0.5f * HH, 0.5f * HH - 0.5f);

    // per-tap pixel-space steps
    const float cstep = (0.5f * WW) / (6.0f * 99.0f);
    float ux = t00 * cstep, uy = t10 * cstep;
    float vx = t01 * cstep, vy = t11 * cstep;

    // separable 1D blur weights
    float wk[11];
    float wsum = 0.0f;
#pragma unroll
    for (int k = 0; k < 11; k++) {
        float d = (float)(k - 5) * (1.0f / 6.0f);
        wk[k] = expf(-8.0f * d * d);
        wsum += wk[k];
    }
    float inv = 1.0f / (wsum * wsum);

    const uint4* __restrict__ buf = g_packed + (b << 16);  // b * 256 rows * 256

    float acc0 = 0.0f, acc1 = 0.0f, acc2 = 0.0f;

#pragma unroll 1
    for (int ky = half; ky < 11; ky += 2) {
        float dky = (float)(ky - 5);
        float dd = dky * (1.0f / 6.0f);
        float wyk = expf(-8.0f * dd * dd);
        float ixr = fmaf(dky, vx, ixb);
        float iyr = fmaf(dky, vy, iyb);
#pragma unroll
        for (int kx = 0; kx < 11; kx++) {
            float dkx = (float)(kx - 5);
            float ix = fmaf(dkx, ux, ixr);
            float iy = fmaf(dkx, uy, iyr);

            float x0f = floorf(ix);
            float y0f = floorf(iy);
            float fx = ix - x0f;
            float fy = iy - y0f;
            int x0 = (int)x0f;
            int y0 = (int)y0f;
            int y1 = y0 + 1;

            // y: validity folded into weights; clamped row index (weight 0 if OOB)
            float wy0 = ((unsigned)y0 < (unsigned)HH) ? (1.0f - fy) : 0.0f;
            float wy1 = ((unsigned)y1 < (unsigned)HH) ? fy : 0.0f;
            int yc0 = min(max(y0, 0), HH - 1);
            int yc1 = min(max(y1, 0), HH - 1);

            // x: clamp pair start, shift-remap the two bilinear weights
            int xp = min(max(x0, 0), WW - 2);
            int s = xp - x0;  // 0 normal; 1 if x0=-1; -1 if x0=255; |s|>=2 fully OOB
            float w_lo = (s == 0) ? (1.0f - fx) : ((s == 1) ? fx : 0.0f);
            float w_hi = (s == 0) ? fx : ((s == -1) ? (1.0f - fx) : 0.0f);

            int col = ((xp & 1) << 7) | (xp >> 1);
            uint4 q0 = buf[(yc0 << 8) + col];  // pixels (xp, xp+1) at row yc0
            uint4 q1 = buf[(yc1 << 8) + col];  // pixels (xp, xp+1) at row yc1

            float wgt = wyk * wk[kx];
            float a0 = wy0 * wgt;
            float a1 = wy1 * wgt;
            float wl0 = a0 * w_lo, wh0 = a0 * w_hi;
            float wl1 = a1 * w_lo, wh1 = a1 * w_hi;

            accum(q0.x, q0.y, wl0, acc0, acc1, acc2);
            accum(q0.z, q0.w, wh0, acc0, acc1, acc2);
            accum(q1.x, q1.y, wl1, acc0, acc1, acc2);
            accum(q1.z, q1.w, wh1, acc0, acc1, acc2);
        }
    }

    // reduce the two ky-halves (lane pairs)
    acc0 += __shfl_xor_sync(0xffffffff, acc0, 1);
    acc1 += __shfl_xor_sync(0xffffffff, acc1, 1);
    acc2 += __shfl_xor_sync(0xffffffff, acc2, 1);

    if (half == 0) {
        float* ob = out + b * (CC * MM * MM) + r;
        ob[0]           = acc0 * inv;
        ob[MM * MM]     = acc1 * inv;
        ob[2 * MM * MM] = acc2 * inv;
    }
}

extern "C" void kernel_launch(void* const* d_in, const int* in_sizes, int n_in,
                              void* d_out, int out_size) {
    const float* x = (const float*)d_in[0];
    const float* th = (const float*)d_in[1];
    if (n_in >= 2 && in_sizes[0] == 96) {
        x = (const float*)d_in[1];
        th = (const float*)d_in[0];
    }
    float* out = (float*)d_out;

    {
        int n = BB * HW;
        int tpb = 256;
        pack_kernel<<<(n + tpb - 1) / tpb, tpb>>>(x);
    }
    {
        int n = OUT_PIX * 2;
        int tpb = 128;
        stn_kernel<<<(n + tpb - 1) / tpb, tpb>>>(th, out);
    }
    (void)out_size;
}